// round 8
// baseline (speedup 1.0000x reference)
#include <cuda_runtime.h>
#include <math.h>

#define B_  256
#define T_  512
#define I_  256
#define H_  512
#define G3  1536   // 3*H

// ---------------- scratch (device globals: no allocation allowed) ----------
__device__ __align__(16) float g_igates[(size_t)T_ * B_ * G3]; // (t,b,g)
__device__ __align__(16) float g_h2[2][B_ * H_];               // double-buffered h
__device__ unsigned g_bar;                                     // global barrier ctr

// ---------------- packed fp32x2 FMA (sm_100a+/103a) ------------------------
__device__ __forceinline__ unsigned long long ffma2(unsigned long long a,
                                                    unsigned long long b,
                                                    unsigned long long c) {
    unsigned long long d;
    asm("fma.rn.f32x2 %0, %1, %2, %3;" : "=l"(d) : "l"(a), "l"(b), "l"(c));
    return d;
}
__device__ __forceinline__ float pairsum(unsigned long long v) {
    float lo = __uint_as_float((unsigned int)(v & 0xffffffffull));
    float hi = __uint_as_float((unsigned int)(v >> 32));
    return lo + hi;
}
// 16B global load -> two 8B SMEM stores (row stride 280B is 8B- but not
// 16B-aligned; STS.128 would trap "misaligned address").
__device__ __forceinline__ void stage16(float* dst, const float* src) {
    float4 v = *(const float4*)src;
    *(float2*)(dst + 0) = make_float2(v.x, v.y);
    *(float2*)(dst + 2) = make_float2(v.z, v.w);
}

// ======================= Kernel 1: igates GEMM ==============================
// igates[t][b][g] = sum_i x[b][t][i] * w_ih[g][i] + bias[g]
// M = B*T (row m = b*T + t), N = 1536, K = 256.
__global__ __launch_bounds__(256) void igates_kernel(
        const float* __restrict__ x, const float* __restrict__ w_ih,
        const float* __restrict__ bias) {
    __shared__ __align__(16) float xs[64][70];  // stride 70 == 6 mod 32
    __shared__ __align__(16) float ws[64][70];

    const int tid = threadIdx.x;
    const int tx = tid & 15;
    const int ty = tid >> 4;
    const int n0 = blockIdx.x * 64;
    const int m0 = blockIdx.y * 64;

    unsigned long long acc[4][4];
#pragma unroll
    for (int i = 0; i < 4; i++)
#pragma unroll
        for (int j = 0; j < 4; j++) acc[i][j] = 0ull;

    for (int kc = 0; kc < 4; kc++) {
        const int kb = kc * 64;
#pragma unroll
        for (int q = 0; q < 4; q++) {
            int qi = tid + 256 * q;
            int r = qi >> 4, kq = qi & 15;
            stage16(&xs[r][kq * 4], &x[(size_t)(m0 + r) * I_ + kb + kq * 4]);
            stage16(&ws[r][kq * 4], &w_ih[(size_t)(n0 + r) * I_ + kb + kq * 4]);
        }
        __syncthreads();
#pragma unroll 4
        for (int k2 = 0; k2 < 32; k2++) {
            unsigned long long xv[4], wv[4];
#pragma unroll
            for (int i = 0; i < 4; i++)
                xv[i] = *(const unsigned long long*)&xs[ty + 16 * i][2 * k2];
#pragma unroll
            for (int j = 0; j < 4; j++)
                wv[j] = *(const unsigned long long*)&ws[tx + 16 * j][2 * k2];
#pragma unroll
            for (int i = 0; i < 4; i++)
#pragma unroll
                for (int j = 0; j < 4; j++)
                    acc[i][j] = ffma2(xv[i], wv[j], acc[i][j]);
        }
        __syncthreads();
    }
#pragma unroll
    for (int i = 0; i < 4; i++) {
        int m = m0 + ty + 16 * i;
        int t = m & (T_ - 1);
        int bb = m >> 9;
        size_t base = ((size_t)t * B_ + bb) * G3;
#pragma unroll
        for (int j = 0; j < 4; j++) {
            int n = n0 + tx + 16 * j;
            g_igates[base + n] = pairsum(acc[i][j]) + bias[n];
        }
    }
}

// ============== Kernel 2: persistent GRU recurrence (512 steps) =============
// Grid: 128 blocks x 128 threads -> one block per SM, all co-resident, so a
// global atomic barrier per step is deadlock-free. Block owns (32 b x 32 j)
// for all 3 gates with full K=512 -> pointwise applied in-register.
#define NBLK 128
__global__ __launch_bounds__(128) void recur_kernel(
        const float* __restrict__ w_hh, const float* __restrict__ b_n) {
    __shared__ __align__(16) float hs[32][70];
    __shared__ __align__(16) float ws[96][70];

    const int tid = threadIdx.x;
    const int tx = tid & 15;             // j-group
    const int ty = tid >> 4;             // b-group (0..7)
    const int j0 = (blockIdx.x & 15) * 32;
    const int b0 = (blockIdx.x >> 4) * 32;

    for (int t = 0; t < T_; t++) {
        const float* __restrict__ hprev = g_h2[t & 1];
        float* __restrict__ hnext = g_h2[(t + 1) & 1];

        unsigned long long acc[4][3][2];
#pragma unroll
        for (int i = 0; i < 4; i++)
#pragma unroll
            for (int g = 0; g < 3; g++) { acc[i][g][0] = 0ull; acc[i][g][1] = 0ull; }

        for (int kc = 0; kc < 8; kc++) {            // K = 512 in chunks of 64
            const int kb = kc * 64;
#pragma unroll
            for (int q = 0; q < 4; q++) {           // h tile: 32 x 16 float4
                int qi = tid + 128 * q;
                int r = qi >> 4, kq = qi & 15;
                stage16(&hs[r][kq * 4], &hprev[(size_t)(b0 + r) * H_ + kb + kq * 4]);
            }
#pragma unroll
            for (int q = 0; q < 12; q++) {          // w tile: 96 x 16 float4
                int qi = tid + 128 * q;
                int r = qi >> 4, kq = qi & 15;
                int gr = (r >> 5) * H_ + j0 + (r & 31);
                stage16(&ws[r][kq * 4], &w_hh[(size_t)gr * H_ + kb + kq * 4]);
            }
            __syncthreads();
#pragma unroll 4
            for (int k2 = 0; k2 < 32; k2++) {
                unsigned long long hv[4], wv[3][2];
#pragma unroll
                for (int i = 0; i < 4; i++)
                    hv[i] = *(const unsigned long long*)&hs[ty + 8 * i][2 * k2];
#pragma unroll
                for (int g = 0; g < 3; g++)
#pragma unroll
                    for (int jl = 0; jl < 2; jl++)
                        wv[g][jl] = *(const unsigned long long*)
                            &ws[g * 32 + tx + 16 * jl][2 * k2];
#pragma unroll
                for (int i = 0; i < 4; i++)
#pragma unroll
                    for (int g = 0; g < 3; g++)
#pragma unroll
                        for (int jl = 0; jl < 2; jl++)
                            acc[i][g][jl] = ffma2(hv[i], wv[g][jl], acc[i][g][jl]);
            }
            __syncthreads();
        }

        // ---- GRU pointwise, in registers ----
#pragma unroll
        for (int i = 0; i < 4; i++) {
            int b = b0 + ty + 8 * i;
            size_t ib = ((size_t)t * B_ + b) * G3;
#pragma unroll
            for (int jl = 0; jl < 2; jl++) {
                int j = j0 + tx + 16 * jl;
                float sr = pairsum(acc[i][0][jl]);
                float sz = pairsum(acc[i][1][jl]);
                float sn = pairsum(acc[i][2][jl]);
                float ir = g_igates[ib + j];
                float iz = g_igates[ib + H_ + j];
                float in_ = g_igates[ib + 2 * H_ + j];
                float h = hprev[b * H_ + j];
                float r = 1.0f / (1.0f + expf(-(ir + sr)));
                float z = 1.0f / (1.0f + expf(-(iz + sz)));
                float n = tanhf(in_ + r * (sn + b_n[j]));
                hnext[b * H_ + j] = n + z * (h - n);
            }
        }

        // ---- device-wide barrier (all 128 blocks resident) ----
        __threadfence();
        __syncthreads();
        if (tid == 0) {
            atomicAdd(&g_bar, 1u);
            unsigned target = (unsigned)(t + 1) * NBLK;
            volatile unsigned* p = &g_bar;
            while (*p < target) { }
        }
        __syncthreads();
        __threadfence();
    }
}

// ======================= Kernel 3: final projection =========================
__global__ __launch_bounds__(128) void proj_kernel(
        const float* __restrict__ w_proj, const float* __restrict__ b_proj,
        float* __restrict__ out) {
    __shared__ float red[4];
    int b = blockIdx.x;
    float s = 0.f;
    for (int j = threadIdx.x; j < H_; j += 128)
        s += g_h2[0][b * H_ + j] * w_proj[j];   // T=512 even -> final h in buf 0
#pragma unroll
    for (int o = 16; o; o >>= 1) s += __shfl_down_sync(0xffffffffu, s, o);
    if ((threadIdx.x & 31) == 0) red[threadIdx.x >> 5] = s;
    __syncthreads();
    if (threadIdx.x == 0)
        out[b] = red[0] + red[1] + red[2] + red[3] + b_proj[0];
}

__global__ void zero_kernel() {
    int i = blockIdx.x * 256 + threadIdx.x;
    if (i < B_ * H_) g_h2[0][i] = 0.f;
    if (i == 0) g_bar = 0u;     // reset barrier counter every launch/replay
}

// ======================= launch ============================================
extern "C" void kernel_launch(void* const* d_in, const int* in_sizes, int n_in,
                              void* d_out, int out_size) {
    const float* x      = (const float*)d_in[0];  // (B,T,I)
    const float* w_ih   = (const float*)d_in[1];  // (3H,I)
    const float* w_hh   = (const float*)d_in[2];  // (3H,H)
    const float* b      = (const float*)d_in[3];  // (3H)
    const float* b_n    = (const float*)d_in[4];  // (H)
    const float* w_proj = (const float*)d_in[5];  // (1,H)
    const float* b_proj = (const float*)d_in[6];  // (1)
    float* out = (float*)d_out;                   // (B)

    igates_kernel<<<dim3(G3 / 64, (B_ * T_) / 64), 256>>>(x, w_ih, b);
    zero_kernel<<<(B_ * H_) / 256, 256>>>();
    recur_kernel<<<NBLK, 128>>>(w_hh, b_n);
    proj_kernel<<<B_, 128>>>(w_proj, b_proj, out);
}

// round 9
// speedup vs baseline: 1.1721x; 1.1721x over previous
#include <cuda_runtime.h>
#include <math.h>

#define B_  256
#define T_  512
#define I_  256
#define H_  512
#define G3  1536   // 3*H
#define NBLK 128

// ---------------- scratch (device globals: no allocation allowed) ----------
__device__ __align__(16) float g_igates[(size_t)T_ * B_ * G3]; // (t,b,g)
__device__ __align__(16) float g_h2[2][B_ * H_];               // double-buffered h
__device__ unsigned g_bar;                                     // global barrier ctr

// ---------------- packed fp32x2 FMA (sm_100a+/103a) ------------------------
__device__ __forceinline__ unsigned long long ffma2(unsigned long long a,
                                                    unsigned long long b,
                                                    unsigned long long c) {
    unsigned long long d;
    asm("fma.rn.f32x2 %0, %1, %2, %3;" : "=l"(d) : "l"(a), "l"(b), "l"(c));
    return d;
}
__device__ __forceinline__ float pairsum(unsigned long long v) {
    float lo = __uint_as_float((unsigned int)(v & 0xffffffffull));
    float hi = __uint_as_float((unsigned int)(v >> 32));
    return lo + hi;
}
// 16B global load -> two 8B SMEM stores (row strides are 8B- but not 16B-
// aligned; STS.128 would trap "misaligned address").
__device__ __forceinline__ void stage16(float* dst, const float* src) {
    float4 v = *(const float4*)src;
    *(float2*)(dst + 0) = make_float2(v.x, v.y);
    *(float2*)(dst + 2) = make_float2(v.z, v.w);
}
__device__ __forceinline__ void sts16(float* dst, float4 v) {
    *(float2*)(dst + 0) = make_float2(v.x, v.y);
    *(float2*)(dst + 2) = make_float2(v.z, v.w);
}

// ======================= Kernel 1: igates GEMM ==============================
// igates[t][b][g] = sum_i x[b][t][i] * w_ih[g][i] + bias[g]
__global__ __launch_bounds__(256) void igates_kernel(
        const float* __restrict__ x, const float* __restrict__ w_ih,
        const float* __restrict__ bias) {
    __shared__ __align__(16) float xs[64][70];  // stride 70 == 6 mod 32
    __shared__ __align__(16) float ws[64][70];

    const int tid = threadIdx.x;
    const int tx = tid & 15;
    const int ty = tid >> 4;
    const int n0 = blockIdx.x * 64;
    const int m0 = blockIdx.y * 64;

    unsigned long long acc[4][4];
#pragma unroll
    for (int i = 0; i < 4; i++)
#pragma unroll
        for (int j = 0; j < 4; j++) acc[i][j] = 0ull;

    for (int kc = 0; kc < 4; kc++) {
        const int kb = kc * 64;
#pragma unroll
        for (int q = 0; q < 4; q++) {
            int qi = tid + 256 * q;
            int r = qi >> 4, kq = qi & 15;
            stage16(&xs[r][kq * 4], &x[(size_t)(m0 + r) * I_ + kb + kq * 4]);
            stage16(&ws[r][kq * 4], &w_ih[(size_t)(n0 + r) * I_ + kb + kq * 4]);
        }
        __syncthreads();
#pragma unroll 4
        for (int k2 = 0; k2 < 32; k2++) {
            unsigned long long xv[4], wv[4];
#pragma unroll
            for (int i = 0; i < 4; i++)
                xv[i] = *(const unsigned long long*)&xs[ty + 16 * i][2 * k2];
#pragma unroll
            for (int j = 0; j < 4; j++)
                wv[j] = *(const unsigned long long*)&ws[tx + 16 * j][2 * k2];
#pragma unroll
            for (int i = 0; i < 4; i++)
#pragma unroll
                for (int j = 0; j < 4; j++)
                    acc[i][j] = ffma2(xv[i], wv[j], acc[i][j]);
        }
        __syncthreads();
    }
#pragma unroll
    for (int i = 0; i < 4; i++) {
        int m = m0 + ty + 16 * i;
        int t = m & (T_ - 1);
        int bb = m >> 9;
        size_t base = ((size_t)t * B_ + bb) * G3;
#pragma unroll
        for (int j = 0; j < 4; j++) {
            int n = n0 + tx + 16 * j;
            g_igates[base + n] = pairsum(acc[i][j]) + bias[n];
        }
    }
}

// ============== Kernel 2: persistent GRU recurrence (512 steps) =============
// 128 blocks x 256 threads, one block/SM (217KB SMEM), all co-resident.
// w_hh tile (96 rows x 512 K) is loaded into SMEM ONCE and stays resident;
// per step only the 32x512 h tile streams through double-buffered SMEM chunks.
#define WS_STRIDE 518                 // == 6 mod 32 floats, 8B-aligned rows
#define HS_STRIDE 70
#define WS_FLOATS (96 * WS_STRIDE)    // 49728
#define HS_FLOATS (32 * HS_STRIDE)    // 2240
#define SMEM_BYTES ((WS_FLOATS + 2 * HS_FLOATS) * 4)   // 216832 B

__global__ __launch_bounds__(256) void recur_kernel(
        const float* __restrict__ w_hh, const float* __restrict__ b_n) {
    extern __shared__ float smem[];
    float* ws = smem;                          // [96][WS_STRIDE]
    float* hs = smem + WS_FLOATS;              // [2][32][HS_STRIDE]

    const int tid = threadIdx.x;
    const int tx = tid & 15;                   // j-sub
    const int ty = (tid >> 4) & 7;             // b-group
    const int tz = tid >> 7;                   // j-half (0/1)
    const int j0 = (blockIdx.x & 15) * 32;
    const int b0 = (blockIdx.x >> 4) * 32;
    const int jj = tx + 16 * tz;               // 0..31 within tile
    const int jg = j0 + jj;                    // global j

    // ---- load stationary w tile: rows 0..95 = gate g rows j0..j0+31 --------
    for (int q = 0; q < 48; q++) {
        int qi = tid + 256 * q;                // [0, 12288) float4 ids
        int r = qi >> 7;                       // 0..95
        int c4 = qi & 127;                     // float4 col 0..127
        int grow = (r >> 5) * H_ + j0 + (r & 31);
        stage16(&ws[r * WS_STRIDE + c4 * 4],
                &w_hh[(size_t)grow * H_ + c4 * 4]);
    }

    float bnv = b_n[jg];
    __syncthreads();

    for (int t = 0; t < T_; t++) {
        const float* __restrict__ hprev = g_h2[t & 1];
        float* __restrict__ hnext = g_h2[(t + 1) & 1];

        // ---- prefetch pointwise operands (independent of the GEMM) --------
        float igv[3][4], hval[4];
#pragma unroll
        for (int i = 0; i < 4; i++) {
            int b = b0 + ty + 8 * i;
            size_t ib = ((size_t)t * B_ + b) * G3;
            igv[0][i] = g_igates[ib + jg];
            igv[1][i] = g_igates[ib + H_ + jg];
            igv[2][i] = g_igates[ib + 2 * H_ + jg];
            hval[i] = hprev[b * H_ + jg];
        }

        // ---- stage h chunk 0 ------------------------------------------------
#pragma unroll
        for (int q = 0; q < 2; q++) {
            int qi = tid + 256 * q;            // [0,512) float4 ids
            int r = qi >> 4, kq = qi & 15;
            stage16(&hs[r * HS_STRIDE + kq * 4],
                    &hprev[(size_t)(b0 + r) * H_ + kq * 4]);
        }
        __syncthreads();

        unsigned long long acc[4][3];
#pragma unroll
        for (int i = 0; i < 4; i++)
#pragma unroll
            for (int g = 0; g < 3; g++) acc[i][g] = 0ull;

        for (int kc = 0; kc < 8; kc++) {
            // prefetch next h chunk into registers (hidden behind compute)
            float4 nv0, nv1;
            int r0 = 0, c0 = 0, r1 = 0, c1 = 0;
            if (kc < 7) {
                int kb = (kc + 1) * 64;
                int qi = tid;
                r0 = qi >> 4; c0 = qi & 15;
                nv0 = *(const float4*)&hprev[(size_t)(b0 + r0) * H_ + kb + c0 * 4];
                qi = tid + 256;
                r1 = qi >> 4; c1 = qi & 15;
                nv1 = *(const float4*)&hprev[(size_t)(b0 + r1) * H_ + kb + c1 * 4];
            }

            const float* hb = hs + (kc & 1) * HS_FLOATS;
            const int wc = kc * 64;
#pragma unroll 4
            for (int k2 = 0; k2 < 32; k2++) {
                unsigned long long hv[4], wv[3];
#pragma unroll
                for (int i = 0; i < 4; i++)
                    hv[i] = *(const unsigned long long*)
                        &hb[(ty + 8 * i) * HS_STRIDE + 2 * k2];
#pragma unroll
                for (int g = 0; g < 3; g++)
                    wv[g] = *(const unsigned long long*)
                        &ws[(g * 32 + jj) * WS_STRIDE + wc + 2 * k2];
#pragma unroll
                for (int i = 0; i < 4; i++)
#pragma unroll
                    for (int g = 0; g < 3; g++)
                        acc[i][g] = ffma2(hv[i], wv[g], acc[i][g]);
            }
            if (kc < 7) {
                float* nb = hs + ((kc + 1) & 1) * HS_FLOATS;
                sts16(&nb[r0 * HS_STRIDE + c0 * 4], nv0);
                sts16(&nb[r1 * HS_STRIDE + c1 * 4], nv1);
            }
            __syncthreads();
        }

        // ---- GRU pointwise in registers ------------------------------------
#pragma unroll
        for (int i = 0; i < 4; i++) {
            int b = b0 + ty + 8 * i;
            float sr = pairsum(acc[i][0]);
            float sz = pairsum(acc[i][1]);
            float sn = pairsum(acc[i][2]);
            float r = 1.0f / (1.0f + expf(-(igv[0][i] + sr)));
            float z = 1.0f / (1.0f + expf(-(igv[1][i] + sz)));
            float n = tanhf(igv[2][i] + r * (sn + bnv));
            hnext[b * H_ + jg] = n + z * (hval[i] - n);
        }

        // ---- device-wide barrier (all 128 blocks resident) -----------------
        __threadfence();
        __syncthreads();
        if (tid == 0) {
            atomicAdd(&g_bar, 1u);
            unsigned target = (unsigned)(t + 1) * NBLK;
            volatile unsigned* p = &g_bar;
            while (*p < target) { }
        }
        __syncthreads();
    }
}

// ======================= Kernel 3: final projection =========================
__global__ __launch_bounds__(128) void proj_kernel(
        const float* __restrict__ w_proj, const float* __restrict__ b_proj,
        float* __restrict__ out) {
    __shared__ float red[4];
    int b = blockIdx.x;
    float s = 0.f;
    for (int j = threadIdx.x; j < H_; j += 128)
        s += g_h2[0][b * H_ + j] * w_proj[j];   // T=512 even -> final h in buf 0
#pragma unroll
    for (int o = 16; o; o >>= 1) s += __shfl_down_sync(0xffffffffu, s, o);
    if ((threadIdx.x & 31) == 0) red[threadIdx.x >> 5] = s;
    __syncthreads();
    if (threadIdx.x == 0)
        out[b] = red[0] + red[1] + red[2] + red[3] + b_proj[0];
}

__global__ void zero_kernel() {
    int i = blockIdx.x * 256 + threadIdx.x;
    if (i < B_ * H_) g_h2[0][i] = 0.f;
    if (i == 0) g_bar = 0u;     // reset barrier counter every launch/replay
}

// ======================= launch ============================================
extern "C" void kernel_launch(void* const* d_in, const int* in_sizes, int n_in,
                              void* d_out, int out_size) {
    const float* x      = (const float*)d_in[0];  // (B,T,I)
    const float* w_ih   = (const float*)d_in[1];  // (3H,I)
    const float* w_hh   = (const float*)d_in[2];  // (3H,H)
    const float* b      = (const float*)d_in[3];  // (3H)
    const float* b_n    = (const float*)d_in[4];  // (H)
    const float* w_proj = (const float*)d_in[5];  // (1,H)
    const float* b_proj = (const float*)d_in[6];  // (1)
    float* out = (float*)d_out;                   // (B)

    cudaFuncSetAttribute(recur_kernel,
                         cudaFuncAttributeMaxDynamicSharedMemorySize,
                         SMEM_BYTES);

    igates_kernel<<<dim3(G3 / 64, (B_ * T_) / 64), 256>>>(x, w_ih, b);
    zero_kernel<<<(B_ * H_) / 256, 256>>>();
    recur_kernel<<<NBLK, 256, SMEM_BYTES>>>(w_hh, b_n);
    proj_kernel<<<B_, 128>>>(w_proj, b_proj, out);
}